// round 6
// baseline (speedup 1.0000x reference)
#include <cuda_runtime.h>

// PhiCell: Phi is identity => outputs = inputs * k; new_state = outputs[T-1].
// Specialized exact-cover kernel: 512 blocks x 256 threads x 8 float4 each,
// no bounds checks -> addresses are base + immediate offsets, true 8-deep
// front-batched LDG.128 (register budget allows all 8 vectors in flight).

#define VPT 8
#define THREADS 256

__global__ void __launch_bounds__(THREADS) phicell_exact(
    const float4* __restrict__ in4,
    const float*  __restrict__ kptr,
    float4*       __restrict__ out4,
    int n, int out_size)
{
    // Block-contiguous tile: block b owns float4s [b*2048, (b+1)*2048)
    const int base = blockIdx.x * (THREADS * VPT) + threadIdx.x;
    const float4* ip = in4 + base;
    float4*       op = out4 + base;

    float4 v0 = ip[0 * THREADS];
    float4 v1 = ip[1 * THREADS];
    float4 v2 = ip[2 * THREADS];
    float4 v3 = ip[3 * THREADS];
    float4 v4 = ip[4 * THREADS];
    float4 v5 = ip[5 * THREADS];
    float4 v6 = ip[6 * THREADS];
    float4 v7 = ip[7 * THREADS];

    const float k = __ldg(kptr);

    v0.x *= k; v0.y *= k; v0.z *= k; v0.w *= k;
    v1.x *= k; v1.y *= k; v1.z *= k; v1.w *= k;
    v2.x *= k; v2.y *= k; v2.z *= k; v2.w *= k;
    v3.x *= k; v3.y *= k; v3.z *= k; v3.w *= k;
    v4.x *= k; v4.y *= k; v4.z *= k; v4.w *= k;
    v5.x *= k; v5.y *= k; v5.z *= k; v5.w *= k;
    v6.x *= k; v6.y *= k; v6.z *= k; v6.w *= k;
    v7.x *= k; v7.y *= k; v7.z *= k; v7.w *= k;

    op[0 * THREADS] = v0;
    op[1 * THREADS] = v1;
    op[2 * THREADS] = v2;
    op[3 * THREADS] = v3;
    op[4 * THREADS] = v4;
    op[5 * THREADS] = v5;
    op[6 * THREADS] = v6;
    op[7 * THREADS] = v7;

    // Last thread of last block owns the final element -> state slot(s)
    if (base + 7 * THREADS == (n >> 2) - 1) {
        float* outs = (float*)out4;
        for (int s = n; s < out_size; ++s) outs[s] = v7.w;
    }
}

// Generic fallback for any shape (bounds-checked, VPT=4)
__global__ void __launch_bounds__(256) phicell_generic(
    const float* __restrict__ in,
    const float* __restrict__ kptr,
    float*       __restrict__ out,
    int n, int out_size)
{
    const float k = __ldg(kptr);
    const int i = blockIdx.x * blockDim.x + threadIdx.x;
    const int base = i << 2;
    if (base + 3 < n) {
        float4 v = *reinterpret_cast<const float4*>(in + base);
        v.x *= k; v.y *= k; v.z *= k; v.w *= k;
        *reinterpret_cast<float4*>(out + base) = v;
        if (base + 4 == n)
            for (int j = n; j < out_size; ++j) out[j] = v.w;
    } else if (base < n) {
        float last = 0.f;
        for (int idx = base; idx < n; ++idx) { last = in[idx] * k; out[idx] = last; }
        for (int j = n; j < out_size; ++j) out[j] = last;
    }
}

extern "C" void kernel_launch(void* const* d_in, const int* in_sizes, int n_in,
                              void* d_out, int out_size)
{
    const float* in  = (const float*)d_in[0];   // inputs [1, T]
    // d_in[1] = state [1,1] (unused: Phi identity -> output state-independent)
    const float* kpt = (const float*)d_in[2];   // kernel [1,1]
    float* out = (float*)d_out;

    const int n  = in_sizes[0];
    const int per_block = THREADS * VPT * 4;    // elements per block (8192)

    if ((n % per_block) == 0) {
        const int blk = n / per_block;          // 512 for T=4194304
        phicell_exact<<<blk, THREADS>>>(
            (const float4*)in, kpt, (float4*)out, n, out_size);
    } else {
        const int nt  = (n + 3) >> 2;
        const int blk = (nt + 255) / 256;
        phicell_generic<<<blk > 0 ? blk : 1, 256>>>(in, kpt, out, n, out_size);
    }
}